// round 4
// baseline (speedup 1.0000x reference)
#include <cuda_runtime.h>
#include <cstdint>

// Problem constants
#define T_TOK   16384            // B*S
#define H_DIM   2048
#define M_KEYS  8
#define PK_SZ   32
#define V_SZ    128
#define NS_SLOT 16
#define MN      128              // M_KEYS*NS_SLOT
#define EPS_RMS 1e-6f
#define EPS_NRM 1e-12f

// Scratch (static device globals; no allocation)
__device__ float    g_C[MN * H_DIM];        // folded key->slot projection (1MB)
__device__ float    g_P[NS_SLOT * H_DIM];   // emb @ Wout[:V] / M      (128KB)
__device__ float    g_scale[T_TOK];         // rms scales
__device__ unsigned g_idx[T_TOK];           // 8 argmax nibbles per token

// ---------------------------------------------------------------------------
// K1: precompute C[m*16+n][h] = sum_k (slot_norm[m][n][k]) * Wk[m][k][h]
//     and        P[n][h]      = (1/8) sum_v emb[n][v] * Wout[v][h]
// ---------------------------------------------------------------------------
__global__ void k_precompute(const float* __restrict__ Wk,
                             const float* __restrict__ slot,
                             const float* __restrict__ emb,
                             const float* __restrict__ Wout) {
    int b = blockIdx.x;
    int tid = threadIdx.x;
    if (b < MN) {
        int m = b >> 4, n = b & 15;
        __shared__ float s_sln[PK_SZ];
        if (tid < PK_SZ) {
            float v = slot[(m * NS_SLOT + n) * PK_SZ + tid];
            float sq = v * v;
            #pragma unroll
            for (int o = 16; o; o >>= 1) sq += __shfl_xor_sync(0xffffffffu, sq, o);
            float nrm = fmaxf(sqrtf(sq), EPS_NRM);
            s_sln[tid] = v / nrm;
        }
        __syncthreads();
        for (int hh = tid; hh < H_DIM; hh += blockDim.x) {
            float acc = 0.f;
            #pragma unroll
            for (int k = 0; k < PK_SZ; k++)
                acc += s_sln[k] * Wk[(size_t)(m * PK_SZ + k) * H_DIM + hh];
            g_C[(size_t)b * H_DIM + hh] = acc;
        }
    } else {
        int n = b - MN;
        __shared__ float s_e[V_SZ];
        if (tid < V_SZ) s_e[tid] = emb[n * V_SZ + tid] * (1.0f / (float)M_KEYS);
        __syncthreads();
        for (int hh = tid; hh < H_DIM; hh += blockDim.x) {
            float acc = 0.f;
            #pragma unroll 8
            for (int v = 0; v < V_SZ; v++)
                acc += s_e[v] * Wout[(size_t)v * H_DIM + hh];
            g_P[(size_t)n * H_DIM + hh] = acc;
        }
    }
}

// ---------------------------------------------------------------------------
// K2: per-token RMS scale = rsqrt(mean(x^2) + eps)
// ---------------------------------------------------------------------------
__global__ void k_rms(const float* __restrict__ x) {
    int t = blockIdx.x;
    const float4* xr = reinterpret_cast<const float4*>(x) + (size_t)t * (H_DIM / 4);
    int tid = threadIdx.x;
    float4 a = xr[tid];
    float4 b = xr[tid + 256];
    float s = a.x * a.x + a.y * a.y + a.z * a.z + a.w * a.w
            + b.x * b.x + b.y * b.y + b.z * b.z + b.w * b.w;
    #pragma unroll
    for (int o = 16; o; o >>= 1) s += __shfl_xor_sync(0xffffffffu, s, o);
    __shared__ float sw[8];
    if ((tid & 31) == 0) sw[tid >> 5] = s;
    __syncthreads();
    if (tid < 8) {
        float v = sw[tid];
        #pragma unroll
        for (int o = 4; o; o >>= 1) v += __shfl_xor_sync(0x000000ffu, v, o);
        if (tid == 0) g_scale[t] = rsqrtf(v * (1.0f / (float)H_DIM) + EPS_RMS);
    }
}

// ---------------------------------------------------------------------------
// K3: sims GEMM (64 tokens x 128 mn x K=2048) + per-(token,m) argmax over 16
//     A[t][k] = x[t][k] * scale[t] * ln_w[k] ; B = g_C (row-major [mn][k])
//     argmax is scale-invariant -> no kp normalization needed.
// ---------------------------------------------------------------------------
__global__ __launch_bounds__(256, 2)
void k_sims(const float* __restrict__ x, const float* __restrict__ lnw) {
    __shared__ __align__(16) float As[16][64];
    __shared__ __align__(16) float Cs[16][128];
    __shared__ float s_scale[64];
    __shared__ unsigned s_idx[64];
    __shared__ float s_lnw[H_DIM];

    int tid = threadIdx.x;
    int t0 = blockIdx.x * 64;
    for (int i = tid; i < H_DIM; i += 256) s_lnw[i] = lnw[i];
    if (tid < 64) { s_scale[tid] = g_scale[t0 + tid]; s_idx[tid] = 0u; }
    __syncthreads();

    int tx = tid & 15, ty = tid >> 4;
    float acc[4][8];
    #pragma unroll
    for (int i = 0; i < 4; i++)
        #pragma unroll
        for (int j = 0; j < 8; j++) acc[i][j] = 0.f;

    int arow = tid >> 2, aq = tid & 3;   // A tile: 64 rows x 4 float4
    int crow = tid >> 1, cq = tid & 1;   // C tile: 128 rows x {cq, cq+2} float4

    for (int k0 = 0; k0 < H_DIM; k0 += 16) {
        float4 av = *reinterpret_cast<const float4*>(x + (size_t)(t0 + arow) * H_DIM + k0 + aq * 4);
        float sc = s_scale[arow];
        As[aq * 4 + 0][arow] = av.x * sc * s_lnw[k0 + aq * 4 + 0];
        As[aq * 4 + 1][arow] = av.y * sc * s_lnw[k0 + aq * 4 + 1];
        As[aq * 4 + 2][arow] = av.z * sc * s_lnw[k0 + aq * 4 + 2];
        As[aq * 4 + 3][arow] = av.w * sc * s_lnw[k0 + aq * 4 + 3];
        #pragma unroll
        for (int u = 0; u < 2; u++) {
            int q = cq + u * 2;
            float4 cv = *reinterpret_cast<const float4*>(g_C + (size_t)crow * H_DIM + k0 + q * 4);
            Cs[q * 4 + 0][crow] = cv.x;
            Cs[q * 4 + 1][crow] = cv.y;
            Cs[q * 4 + 2][crow] = cv.z;
            Cs[q * 4 + 3][crow] = cv.w;
        }
        __syncthreads();
        #pragma unroll
        for (int k = 0; k < 16; k++) {
            float4 a0 = *reinterpret_cast<const float4*>(&As[k][ty * 4]);
            float4 b0 = *reinterpret_cast<const float4*>(&Cs[k][tx * 8]);
            float4 b1 = *reinterpret_cast<const float4*>(&Cs[k][tx * 8 + 4]);
            float ra[4] = {a0.x, a0.y, a0.z, a0.w};
            float rb[8] = {b0.x, b0.y, b0.z, b0.w, b1.x, b1.y, b1.z, b1.w};
            #pragma unroll
            for (int i = 0; i < 4; i++)
                #pragma unroll
                for (int j = 0; j < 8; j++)
                    acc[i][j] += ra[i] * rb[j];
        }
        __syncthreads();
    }

    // argmax: thread covers 8 of the 16 slots of m = tx>>1; partner tx^1 has other 8.
    #pragma unroll
    for (int i = 0; i < 4; i++) {
        float bv = acc[i][0];
        int bn = 0;
        #pragma unroll
        for (int j = 1; j < 8; j++)
            if (acc[i][j] > bv) { bv = acc[i][j]; bn = j; }
        float pv = __shfl_xor_sync(0xffffffffu, bv, 1);
        int   pn = __shfl_xor_sync(0xffffffffu, bn, 1);
        if ((tx & 1) == 0) {
            // strict > : ties resolve to lower n (first occurrence, like jnp.argmax)
            int nf = (pv > bv) ? (pn + 8) : bn;
            atomicOr(&s_idx[ty * 4 + i], ((unsigned)nf) << (4 * (tx >> 1)));
        }
    }
    __syncthreads();
    if (tid < 64) g_idx[t0 + tid] = s_idx[tid];
}

// ---------------------------------------------------------------------------
// K4: out = h @ Wout[V:,:]  + x + sum_m P[idx_m]   (128x128x16 SGEMM tile)
// ---------------------------------------------------------------------------
__global__ __launch_bounds__(256, 2)
void k_gemm(const float* __restrict__ x, const float* __restrict__ lnw,
            const float* __restrict__ Wout, float* __restrict__ out) {
    __shared__ __align__(16) float As[16][128];
    __shared__ __align__(16) float Bs[16][128];
    __shared__ float s_scale[128];
    __shared__ float s_lnw[H_DIM];

    int tid = threadIdx.x;
    int m0 = blockIdx.y * 128;
    int n0 = blockIdx.x * 128;
    for (int i = tid; i < H_DIM; i += 256) s_lnw[i] = lnw[i];
    if (tid < 128) s_scale[tid] = g_scale[m0 + tid];
    __syncthreads();

    int tx = tid & 15, ty = tid >> 4;
    float acc[8][8];
    #pragma unroll
    for (int i = 0; i < 8; i++)
        #pragma unroll
        for (int j = 0; j < 8; j++) acc[i][j] = 0.f;

    int arow = tid >> 1;     // 0..127
    int brow = tid >> 4;     // k row 0..15
    int bq0  = tid & 15;     // float4 slots {bq0, bq0+16}
    const float* Bbase = Wout + (size_t)V_SZ * H_DIM + n0;

    for (int k0 = 0; k0 < H_DIM; k0 += 16) {
        float sc = s_scale[arow];
        #pragma unroll
        for (int u = 0; u < 2; u++) {
            int q = (tid & 1) + u * 2;
            float4 av = *reinterpret_cast<const float4*>(x + (size_t)(m0 + arow) * H_DIM + k0 + q * 4);
            As[q * 4 + 0][arow] = av.x * sc * s_lnw[k0 + q * 4 + 0];
            As[q * 4 + 1][arow] = av.y * sc * s_lnw[k0 + q * 4 + 1];
            As[q * 4 + 2][arow] = av.z * sc * s_lnw[k0 + q * 4 + 2];
            As[q * 4 + 3][arow] = av.w * sc * s_lnw[k0 + q * 4 + 3];
        }
        #pragma unroll
        for (int u = 0; u < 2; u++) {
            int q = bq0 + u * 16;
            *reinterpret_cast<float4*>(&Bs[brow][q * 4]) =
                *reinterpret_cast<const float4*>(Bbase + (size_t)(k0 + brow) * H_DIM + q * 4);
        }
        __syncthreads();
        #pragma unroll
        for (int k = 0; k < 16; k++) {
            float4 a0 = *reinterpret_cast<const float4*>(&As[k][ty * 8]);
            float4 a1 = *reinterpret_cast<const float4*>(&As[k][ty * 8 + 4]);
            float4 b0 = *reinterpret_cast<const float4*>(&Bs[k][tx * 8]);
            float4 b1 = *reinterpret_cast<const float4*>(&Bs[k][tx * 8 + 4]);
            float ra[8] = {a0.x, a0.y, a0.z, a0.w, a1.x, a1.y, a1.z, a1.w};
            float rb[8] = {b0.x, b0.y, b0.z, b0.w, b1.x, b1.y, b1.z, b1.w};
            #pragma unroll
            for (int i = 0; i < 8; i++)
                #pragma unroll
                for (int j = 0; j < 8; j++)
                    acc[i][j] += ra[i] * rb[j];
        }
        __syncthreads();
    }

    // Epilogue: + x + sum_m P[idx_m]
    #pragma unroll
    for (int i = 0; i < 8; i++) {
        int r = m0 + ty * 8 + i;
        unsigned pack = g_idx[r];
        float pk[8];
        #pragma unroll
        for (int j = 0; j < 8; j++) pk[j] = 0.f;
        #pragma unroll
        for (int mm = 0; mm < 8; mm++) {
            int n = (pack >> (4 * mm)) & 15;
            const float4* pr = reinterpret_cast<const float4*>(g_P + (size_t)n * H_DIM + n0 + tx * 8);
            float4 p0 = pr[0], p1 = pr[1];
            pk[0] += p0.x; pk[1] += p0.y; pk[2] += p0.z; pk[3] += p0.w;
            pk[4] += p1.x; pk[5] += p1.y; pk[6] += p1.z; pk[7] += p1.w;
        }
        const float4* xr = reinterpret_cast<const float4*>(x + (size_t)r * H_DIM + n0 + tx * 8);
        float4 x0 = xr[0], x1 = xr[1];
        float4 o0, o1;
        o0.x = acc[i][0] + pk[0] + x0.x;
        o0.y = acc[i][1] + pk[1] + x0.y;
        o0.z = acc[i][2] + pk[2] + x0.z;
        o0.w = acc[i][3] + pk[3] + x0.w;
        o1.x = acc[i][4] + pk[4] + x1.x;
        o1.y = acc[i][5] + pk[5] + x1.y;
        o1.z = acc[i][6] + pk[6] + x1.z;
        o1.w = acc[i][7] + pk[7] + x1.w;
        float4* orow = reinterpret_cast<float4*>(out + (size_t)r * H_DIM + n0 + tx * 8);
        orow[0] = o0;
        orow[1] = o1;
    }
}

// ---------------------------------------------------------------------------
extern "C" void kernel_launch(void* const* d_in, const int* in_sizes, int n_in,
                              void* d_out, int out_size) {
    const float* x    = (const float*)d_in[0];
    const float* lnw  = (const float*)d_in[1];
    const float* Wk   = (const float*)d_in[2];
    const float* slot = (const float*)d_in[3];
    const float* emb  = (const float*)d_in[4];
    const float* Wout = (const float*)d_in[5];
    float* out = (float*)d_out;

    k_precompute<<<MN + NS_SLOT, 256>>>(Wk, slot, emb, Wout);
    k_rms<<<T_TOK, 256>>>(x);
    k_sims<<<T_TOK / 64, 256>>>(x, lnw);
    dim3 g4(H_DIM / 128, T_TOK / 128);
    k_gemm<<<g4, 256>>>(x, lnw, Wout, out);
}

// round 6
// speedup vs baseline: 1.0015x; 1.0015x over previous
#include <cuda_runtime.h>
#include <cstdint>

// Problem constants
#define T_TOK   16384            // B*S
#define H_DIM   2048
#define M_KEYS  8
#define PK_SZ   32
#define V_SZ    128
#define NS_SLOT 16
#define MN      128              // M_KEYS*NS_SLOT
#define EPS_RMS 1e-6f
#define EPS_NRM 1e-12f

// Scratch (static device globals; no allocation)
__device__ float    g_C[MN * H_DIM];        // folded key->slot projection (1MB)
__device__ float    g_P[NS_SLOT * H_DIM];   // emb @ Wout[:V] / M      (128KB)
__device__ float    g_scale[T_TOK];         // rms scales
__device__ unsigned g_idx[T_TOK];           // 8 argmax nibbles per token

// ---------------------------------------------------------------------------
// K1: precompute C[m*16+n][h] = sum_k (slot_norm[m][n][k]) * Wk[m][k][h]
//     and        P[n][h]      = (1/8) sum_v emb[n][v] * Wout[v][h]
// ---------------------------------------------------------------------------
__global__ void k_precompute(const float* __restrict__ Wk,
                             const float* __restrict__ slot,
                             const float* __restrict__ emb,
                             const float* __restrict__ Wout) {
    int b = blockIdx.x;
    int tid = threadIdx.x;
    if (b < MN) {
        int m = b >> 4, n = b & 15;
        __shared__ float s_sln[PK_SZ];
        if (tid < PK_SZ) {
            float v = slot[(m * NS_SLOT + n) * PK_SZ + tid];
            float sq = v * v;
            #pragma unroll
            for (int o = 16; o; o >>= 1) sq += __shfl_xor_sync(0xffffffffu, sq, o);
            float nrm = fmaxf(sqrtf(sq), EPS_NRM);
            s_sln[tid] = v / nrm;
        }
        __syncthreads();
        for (int hh = tid; hh < H_DIM; hh += blockDim.x) {
            float acc = 0.f;
            #pragma unroll
            for (int k = 0; k < PK_SZ; k++)
                acc += s_sln[k] * Wk[(size_t)(m * PK_SZ + k) * H_DIM + hh];
            g_C[(size_t)b * H_DIM + hh] = acc;
        }
    } else {
        int n = b - MN;
        __shared__ float s_e[V_SZ];
        if (tid < V_SZ) s_e[tid] = emb[n * V_SZ + tid] * (1.0f / (float)M_KEYS);
        __syncthreads();
        for (int hh = tid; hh < H_DIM; hh += blockDim.x) {
            float acc = 0.f;
            #pragma unroll 8
            for (int v = 0; v < V_SZ; v++)
                acc += s_e[v] * Wout[(size_t)v * H_DIM + hh];
            g_P[(size_t)n * H_DIM + hh] = acc;
        }
    }
}

// ---------------------------------------------------------------------------
// K2: per-token RMS scale = rsqrt(mean(x^2) + eps)
// ---------------------------------------------------------------------------
__global__ void k_rms(const float* __restrict__ x) {
    int t = blockIdx.x;
    const float4* xr = reinterpret_cast<const float4*>(x) + (size_t)t * (H_DIM / 4);
    int tid = threadIdx.x;
    float4 a = xr[tid];
    float4 b = xr[tid + 256];
    float s = a.x * a.x + a.y * a.y + a.z * a.z + a.w * a.w
            + b.x * b.x + b.y * b.y + b.z * b.z + b.w * b.w;
    #pragma unroll
    for (int o = 16; o; o >>= 1) s += __shfl_xor_sync(0xffffffffu, s, o);
    __shared__ float sw[8];
    if ((tid & 31) == 0) sw[tid >> 5] = s;
    __syncthreads();
    if (tid < 8) {
        float v = sw[tid];
        #pragma unroll
        for (int o = 4; o; o >>= 1) v += __shfl_xor_sync(0x000000ffu, v, o);
        if (tid == 0) g_scale[t] = rsqrtf(v * (1.0f / (float)H_DIM) + EPS_RMS);
    }
}

// ---------------------------------------------------------------------------
// K3: sims GEMM (64 tokens x 128 mn x K=2048) + per-(token,m) argmax over 16
//     A[t][k] = x[t][k] * scale[t] * ln_w[k] ; B = g_C (row-major [mn][k])
//     argmax is scale-invariant -> no kp normalization needed.
// ---------------------------------------------------------------------------
__global__ __launch_bounds__(256, 2)
void k_sims(const float* __restrict__ x, const float* __restrict__ lnw) {
    __shared__ __align__(16) float As[16][64];
    __shared__ __align__(16) float Cs[16][128];
    __shared__ float s_scale[64];
    __shared__ unsigned s_idx[64];
    __shared__ float s_lnw[H_DIM];

    int tid = threadIdx.x;
    int t0 = blockIdx.x * 64;
    for (int i = tid; i < H_DIM; i += 256) s_lnw[i] = lnw[i];
    if (tid < 64) { s_scale[tid] = g_scale[t0 + tid]; s_idx[tid] = 0u; }
    __syncthreads();

    int tx = tid & 15, ty = tid >> 4;
    float acc[4][8];
    #pragma unroll
    for (int i = 0; i < 4; i++)
        #pragma unroll
        for (int j = 0; j < 8; j++) acc[i][j] = 0.f;

    int arow = tid >> 2, aq = tid & 3;   // A tile: 64 rows x 4 float4
    int crow = tid >> 1, cq = tid & 1;   // C tile: 128 rows x {cq, cq+2} float4

    for (int k0 = 0; k0 < H_DIM; k0 += 16) {
        float4 av = *reinterpret_cast<const float4*>(x + (size_t)(t0 + arow) * H_DIM + k0 + aq * 4);
        float sc = s_scale[arow];
        As[aq * 4 + 0][arow] = av.x * sc * s_lnw[k0 + aq * 4 + 0];
        As[aq * 4 + 1][arow] = av.y * sc * s_lnw[k0 + aq * 4 + 1];
        As[aq * 4 + 2][arow] = av.z * sc * s_lnw[k0 + aq * 4 + 2];
        As[aq * 4 + 3][arow] = av.w * sc * s_lnw[k0 + aq * 4 + 3];
        #pragma unroll
        for (int u = 0; u < 2; u++) {
            int q = cq + u * 2;
            float4 cv = *reinterpret_cast<const float4*>(g_C + (size_t)crow * H_DIM + k0 + q * 4);
            Cs[q * 4 + 0][crow] = cv.x;
            Cs[q * 4 + 1][crow] = cv.y;
            Cs[q * 4 + 2][crow] = cv.z;
            Cs[q * 4 + 3][crow] = cv.w;
        }
        __syncthreads();
        #pragma unroll
        for (int k = 0; k < 16; k++) {
            float4 a0 = *reinterpret_cast<const float4*>(&As[k][ty * 4]);
            float4 b0 = *reinterpret_cast<const float4*>(&Cs[k][tx * 8]);
            float4 b1 = *reinterpret_cast<const float4*>(&Cs[k][tx * 8 + 4]);
            float ra[4] = {a0.x, a0.y, a0.z, a0.w};
            float rb[8] = {b0.x, b0.y, b0.z, b0.w, b1.x, b1.y, b1.z, b1.w};
            #pragma unroll
            for (int i = 0; i < 4; i++)
                #pragma unroll
                for (int j = 0; j < 8; j++)
                    acc[i][j] += ra[i] * rb[j];
        }
        __syncthreads();
    }

    // argmax: thread covers 8 of the 16 slots of m = tx>>1; partner tx^1 has other 8.
    #pragma unroll
    for (int i = 0; i < 4; i++) {
        float bv = acc[i][0];
        int bn = 0;
        #pragma unroll
        for (int j = 1; j < 8; j++)
            if (acc[i][j] > bv) { bv = acc[i][j]; bn = j; }
        float pv = __shfl_xor_sync(0xffffffffu, bv, 1);
        int   pn = __shfl_xor_sync(0xffffffffu, bn, 1);
        if ((tx & 1) == 0) {
            // strict > : ties resolve to lower n (first occurrence, like jnp.argmax)
            int nf = (pv > bv) ? (pn + 8) : bn;
            atomicOr(&s_idx[ty * 4 + i], ((unsigned)nf) << (4 * (tx >> 1)));
        }
    }
    __syncthreads();
    if (tid < 64) g_idx[t0 + tid] = s_idx[tid];
}

// ---------------------------------------------------------------------------
// K4: out = h @ Wout[V:,:]  + x + sum_m P[idx_m]   (128x128x16 SGEMM tile)
// ---------------------------------------------------------------------------
__global__ __launch_bounds__(256, 2)
void k_gemm(const float* __restrict__ x, const float* __restrict__ lnw,
            const float* __restrict__ Wout, float* __restrict__ out) {
    __shared__ __align__(16) float As[16][128];
    __shared__ __align__(16) float Bs[16][128];
    __shared__ float s_scale[128];
    __shared__ float s_lnw[H_DIM];

    int tid = threadIdx.x;
    int m0 = blockIdx.y * 128;
    int n0 = blockIdx.x * 128;
    for (int i = tid; i < H_DIM; i += 256) s_lnw[i] = lnw[i];
    if (tid < 128) s_scale[tid] = g_scale[m0 + tid];
    __syncthreads();

    int tx = tid & 15, ty = tid >> 4;
    float acc[8][8];
    #pragma unroll
    for (int i = 0; i < 8; i++)
        #pragma unroll
        for (int j = 0; j < 8; j++) acc[i][j] = 0.f;

    int arow = tid >> 1;     // 0..127
    int brow = tid >> 4;     // k row 0..15
    int bq0  = tid & 15;     // float4 slots {bq0, bq0+16}
    const float* Bbase = Wout + (size_t)V_SZ * H_DIM + n0;

    for (int k0 = 0; k0 < H_DIM; k0 += 16) {
        float sc = s_scale[arow];
        #pragma unroll
        for (int u = 0; u < 2; u++) {
            int q = (tid & 1) + u * 2;
            float4 av = *reinterpret_cast<const float4*>(x + (size_t)(m0 + arow) * H_DIM + k0 + q * 4);
            As[q * 4 + 0][arow] = av.x * sc * s_lnw[k0 + q * 4 + 0];
            As[q * 4 + 1][arow] = av.y * sc * s_lnw[k0 + q * 4 + 1];
            As[q * 4 + 2][arow] = av.z * sc * s_lnw[k0 + q * 4 + 2];
            As[q * 4 + 3][arow] = av.w * sc * s_lnw[k0 + q * 4 + 3];
        }
        #pragma unroll
        for (int u = 0; u < 2; u++) {
            int q = bq0 + u * 16;
            *reinterpret_cast<float4*>(&Bs[brow][q * 4]) =
                *reinterpret_cast<const float4*>(Bbase + (size_t)(k0 + brow) * H_DIM + q * 4);
        }
        __syncthreads();
        #pragma unroll
        for (int k = 0; k < 16; k++) {
            float4 a0 = *reinterpret_cast<const float4*>(&As[k][ty * 8]);
            float4 a1 = *reinterpret_cast<const float4*>(&As[k][ty * 8 + 4]);
            float4 b0 = *reinterpret_cast<const float4*>(&Bs[k][tx * 8]);
            float4 b1 = *reinterpret_cast<const float4*>(&Bs[k][tx * 8 + 4]);
            float ra[8] = {a0.x, a0.y, a0.z, a0.w, a1.x, a1.y, a1.z, a1.w};
            float rb[8] = {b0.x, b0.y, b0.z, b0.w, b1.x, b1.y, b1.z, b1.w};
            #pragma unroll
            for (int i = 0; i < 8; i++)
                #pragma unroll
                for (int j = 0; j < 8; j++)
                    acc[i][j] += ra[i] * rb[j];
        }
        __syncthreads();
    }

    // Epilogue: + x + sum_m P[idx_m]
    #pragma unroll
    for (int i = 0; i < 8; i++) {
        int r = m0 + ty * 8 + i;
        unsigned pack = g_idx[r];
        float pk[8];
        #pragma unroll
        for (int j = 0; j < 8; j++) pk[j] = 0.f;
        #pragma unroll
        for (int mm = 0; mm < 8; mm++) {
            int n = (pack >> (4 * mm)) & 15;
            const float4* pr = reinterpret_cast<const float4*>(g_P + (size_t)n * H_DIM + n0 + tx * 8);
            float4 p0 = pr[0], p1 = pr[1];
            pk[0] += p0.x; pk[1] += p0.y; pk[2] += p0.z; pk[3] += p0.w;
            pk[4] += p1.x; pk[5] += p1.y; pk[6] += p1.z; pk[7] += p1.w;
        }
        const float4* xr = reinterpret_cast<const float4*>(x + (size_t)r * H_DIM + n0 + tx * 8);
        float4 x0 = xr[0], x1 = xr[1];
        float4 o0, o1;
        o0.x = acc[i][0] + pk[0] + x0.x;
        o0.y = acc[i][1] + pk[1] + x0.y;
        o0.z = acc[i][2] + pk[2] + x0.z;
        o0.w = acc[i][3] + pk[3] + x0.w;
        o1.x = acc[i][4] + pk[4] + x1.x;
        o1.y = acc[i][5] + pk[5] + x1.y;
        o1.z = acc[i][6] + pk[6] + x1.z;
        o1.w = acc[i][7] + pk[7] + x1.w;
        float4* orow = reinterpret_cast<float4*>(out + (size_t)r * H_DIM + n0 + tx * 8);
        orow[0] = o0;
        orow[1] = o1;
    }
}

// ---------------------------------------------------------------------------
extern "C" void kernel_launch(void* const* d_in, const int* in_sizes, int n_in,
                              void* d_out, int out_size) {
    const float* x    = (const float*)d_in[0];
    const float* lnw  = (const float*)d_in[1];
    const float* Wk   = (const float*)d_in[2];
    const float* slot = (const float*)d_in[3];
    const float* emb  = (const float*)d_in[4];
    const float* Wout = (const float*)d_in[5];
    float* out = (float*)d_out;

    k_precompute<<<MN + NS_SLOT, 256>>>(Wk, slot, emb, Wout);
    k_rms<<<T_TOK, 256>>>(x);
    k_sims<<<T_TOK / 64, 256>>>(x, lnw);
    dim3 g4(H_DIM / 128, T_TOK / 128);
    k_gemm<<<g4, 256>>>(x, lnw, Wout, out);
}